// round 1
// baseline (speedup 1.0000x reference)
#include <cuda_runtime.h>
#include <cstdint>
#include <math.h>

// Problem constants
#define HDIM 512
#define G4   2048   // 4*H
#define EDIM 256
#define N_SC 640
#define T_SC 128
#define N_CM 640
#define T_CM 64
#define N_IS 64
#define T_IS 32

// ---------------- scratch (device globals; no allocation allowed) ----------------
__device__ float g_xproj_sc[(size_t)N_SC * T_SC * G4];   // [t][n][4H], bias folded
__device__ float g_xproj_cm[(size_t)N_CM * T_CM * G4];
__device__ float g_xproj_is[(size_t)N_IS * T_IS * G4];

__device__ float g_h_sc[2][N_SC * HDIM];
__device__ float g_c_sc[N_SC * HDIM];
__device__ float g_h_cm[2][N_CM * HDIM];
__device__ float g_c_cm[N_CM * HDIM];
__device__ float g_h_is[2][N_IS * HDIM];
__device__ float g_c_is[N_IS * HDIM];

__device__ float g_hm[N_SC];    // [B*NC] per-commit merged h scalar
__device__ float g_cmm[N_SC];

// ---------------- zero initial states ----------------
__global__ void zero_state() {
    int i = blockIdx.x * blockDim.x + threadIdx.x;
    if (i < N_SC * HDIM) {
        g_h_sc[0][i] = 0.f; g_c_sc[i] = 0.f;
        g_h_cm[0][i] = 0.f; g_c_cm[i] = 0.f;
    }
    if (i < N_IS * HDIM) {
        g_h_is[0][i] = 0.f; g_c_is[i] = 0.f;
    }
}

// ---------------- input projection: out[m][j] = emb[ids[n][t]] . Wih[j] + b[j]
// m = t*N + n  (t-major so each step reads a contiguous [N,4H] slab)
// Tiled GEMM: BM=64, BN=64, BK=32, 256 threads, 4x4 micro-tile (strided map).
__global__ void xproj_kernel(const int* __restrict__ ids,
                             const float* __restrict__ emb,
                             const float* __restrict__ Wih,   // [4H, E]
                             const float* __restrict__ bias,  // [4H]
                             int N, int T, int sel)
{
    float* out = (sel == 0) ? g_xproj_sc : (sel == 1) ? g_xproj_cm : g_xproj_is;

    __shared__ float As[64][33];
    __shared__ float Bs[32][65];
    __shared__ int   tok[64];

    const int m0 = blockIdx.x * 64;
    const int j0 = blockIdx.y * 64;
    const int tid = threadIdx.x;
    const int ty = tid >> 4, tx = tid & 15;

    if (tid < 64) {
        int m = m0 + tid;
        int t = m / N, n = m - t * N;
        tok[tid] = ids[n * T + t];
    }
    __syncthreads();

    float acc[4][4];
#pragma unroll
    for (int i = 0; i < 4; i++)
#pragma unroll
        for (int j = 0; j < 4; j++) acc[i][j] = 0.f;

    for (int k0 = 0; k0 < EDIM; k0 += 32) {
#pragma unroll
        for (int i = 0; i < 8; i++) {
            int lin = tid + i * 256;          // 2048 elems
            int r = lin >> 5, k = lin & 31;
            As[r][k] = emb[(size_t)tok[r] * EDIM + k0 + k];
        }
#pragma unroll
        for (int i = 0; i < 8; i++) {
            int lin = tid + i * 256;          // 2048 elems
            int j = lin >> 5, k = lin & 31;
            Bs[k][j] = Wih[(size_t)(j0 + j) * EDIM + k0 + k];
        }
        __syncthreads();
#pragma unroll
        for (int k = 0; k < 32; k++) {
            float a[4], b[4];
#pragma unroll
            for (int i = 0; i < 4; i++) a[i] = As[ty + 16 * i][k];
#pragma unroll
            for (int j = 0; j < 4; j++) b[j] = Bs[k][tx + 16 * j];
#pragma unroll
            for (int i = 0; i < 4; i++)
#pragma unroll
                for (int j = 0; j < 4; j++) acc[i][j] += a[i] * b[j];
        }
        __syncthreads();
    }

#pragma unroll
    for (int i = 0; i < 4; i++) {
        int m = m0 + ty + 16 * i;
#pragma unroll
        for (int j = 0; j < 4; j++) {
            int jj = j0 + tx + 16 * j;
            out[(size_t)m * G4 + jj] = acc[i][j] + bias[jj];
        }
    }
}

// ---------------- fused LSTM step for all three LSTMs at time t ----------------
// Block tile: 64 rows x 32 gate-cols x 4 gates of z = h@Whh.T, then pointwise.
// Grid: [0,160) sc ; [160,320) cm (if t<64) ; [320,336) is (if t<32)
__global__ void lstm_step_all(int t,
                              const float* __restrict__ Whh_sc,
                              const float* __restrict__ Whh_cm,
                              const float* __restrict__ Whh_is)
{
    __shared__ float As[64][33];
    __shared__ float Bs[4][32][33];

    int bid = blockIdx.x;
    const float* Whh; const float* xp; const float* h_in;
    float* h_out; float* c; int N;

    if (bid < 160) {
        Whh = Whh_sc; N = N_SC;
        xp = g_xproj_sc + (size_t)t * N_SC * G4;
        h_in = g_h_sc[t & 1]; h_out = g_h_sc[(t + 1) & 1]; c = g_c_sc;
    } else if (bid < 320) {
        bid -= 160;
        Whh = Whh_cm; N = N_CM;
        xp = g_xproj_cm + (size_t)t * N_CM * G4;
        h_in = g_h_cm[t & 1]; h_out = g_h_cm[(t + 1) & 1]; c = g_c_cm;
    } else {
        bid -= 320;
        Whh = Whh_is; N = N_IS;
        xp = g_xproj_is + (size_t)t * N_IS * G4;
        h_in = g_h_is[t & 1]; h_out = g_h_is[(t + 1) & 1]; c = g_c_is;
    }
    (void)N;

    const int rt = bid >> 4;          // row tile (64 rows)
    const int ct = bid & 15;          // col tile (32 of 512 gate cols)
    const int m0 = rt * 64;
    const int c0 = ct * 32;
    const int tid = threadIdx.x;
    const int ty = tid >> 4, tx = tid & 15;

    float acc[4][4][2];
#pragma unroll
    for (int g = 0; g < 4; g++)
#pragma unroll
        for (int i = 0; i < 4; i++) { acc[g][i][0] = 0.f; acc[g][i][1] = 0.f; }

    for (int k0 = 0; k0 < HDIM; k0 += 32) {
#pragma unroll
        for (int i = 0; i < 8; i++) {
            int lin = tid + i * 256;          // 64*32 = 2048
            int r = lin >> 5, k = lin & 31;
            As[r][k] = h_in[(size_t)(m0 + r) * HDIM + k0 + k];
        }
#pragma unroll
        for (int i = 0; i < 16; i++) {
            int lin = tid + i * 256;          // 4*32*32 = 4096
            int g = lin >> 10;
            int j = (lin >> 5) & 31;
            int k = lin & 31;
            Bs[g][k][j] = Whh[(size_t)(g * 512 + c0 + j) * HDIM + k0 + k];
        }
        __syncthreads();
#pragma unroll
        for (int k = 0; k < 32; k++) {
            float a[4];
#pragma unroll
            for (int i = 0; i < 4; i++) a[i] = As[ty + 16 * i][k];
#pragma unroll
            for (int g = 0; g < 4; g++) {
                float b0 = Bs[g][k][tx];
                float b1 = Bs[g][k][tx + 16];
#pragma unroll
                for (int i = 0; i < 4; i++) {
                    acc[g][i][0] += a[i] * b0;
                    acc[g][i][1] += a[i] * b1;
                }
            }
        }
        __syncthreads();
    }

    // pointwise epilogue
#pragma unroll
    for (int i = 0; i < 4; i++) {
        int m = m0 + ty + 16 * i;
#pragma unroll
        for (int j = 0; j < 2; j++) {
            int cg = c0 + tx + 16 * j;
            size_t xb = (size_t)m * G4 + cg;
            float zi = acc[0][i][j] + xp[xb];
            float zf = acc[1][i][j] + xp[xb + 512];
            float zg = acc[2][i][j] + xp[xb + 1024];
            float zo = acc[3][i][j] + xp[xb + 1536];
            float ig = 1.f / (1.f + expf(-zi));
            float fg = 1.f / (1.f + expf(-zf));
            float gg = tanhf(zg);
            float og = 1.f / (1.f + expf(-zo));
            size_t hi = (size_t)m * HDIM + cg;
            float cn = fg * c[hi] + ig * gg;
            c[hi] = cn;
            h_out[hi] = og * tanhf(cn);
        }
    }
}

// ---------------- merge: hm[n] = [h_sc|h_cm].Wmh + bmh ; cmm with c-states ------
__global__ void merge_kernel(const float* __restrict__ Wmh, const float* __restrict__ bmh,
                             const float* __restrict__ Wmc, const float* __restrict__ bmc)
{
    int wid = (blockIdx.x * blockDim.x + threadIdx.x) >> 5;
    int lane = threadIdx.x & 31;
    if (wid >= 2 * N_SC) return;
    int which = (wid >= N_SC);
    int n = which ? wid - N_SC : wid;
    const float* W = which ? Wmc : Wmh;
    const float* A = which ? g_c_sc : g_h_sc[0];
    const float* B = which ? g_c_cm : g_h_cm[0];
    float s = 0.f;
    for (int k = lane; k < HDIM; k += 32)
        s += A[(size_t)n * HDIM + k] * W[k] + B[(size_t)n * HDIM + k] * W[HDIM + k];
#pragma unroll
    for (int off = 16; off > 0; off >>= 1) s += __shfl_down_sync(0xffffffffu, s, off);
    if (lane == 0) {
        if (which) g_cmm[n] = s + bmc[0];
        else       g_hm[n]  = s + bmh[0];
    }
}

// ---------------- final: out_h[b][j] = [hm(10)|h_is(512)].Wfh[j] + bfh[j] -------
__global__ void final_kernel(const float* __restrict__ Wfh, const float* __restrict__ bfh,
                             const float* __restrict__ Wfc, const float* __restrict__ bfc,
                             float* __restrict__ out)
{
    int gw = (blockIdx.x * blockDim.x + threadIdx.x) >> 5;
    int lane = threadIdx.x & 31;
    if (gw >= 2 * 64 * HDIM) return;
    int which = (gw >= 64 * HDIM);
    int rem = which ? gw - 64 * HDIM : gw;
    int b = rem >> 9, j = rem & 511;
    const float* W  = which ? Wfc : Wfh;
    const float* mv = which ? g_cmm : g_hm;
    const float* hv = which ? g_c_is : g_h_is[0];
    const int K = 10 + HDIM;   // 522
    float s = 0.f;
    for (int k = lane; k < K; k += 32) {
        float x = (k < 10) ? mv[b * 10 + k] : hv[(size_t)b * HDIM + (k - 10)];
        s += W[(size_t)j * K + k] * x;
    }
#pragma unroll
    for (int off = 16; off > 0; off >>= 1) s += __shfl_down_sync(0xffffffffu, s, off);
    if (lane == 0) {
        float bias = which ? bfc[j] : bfh[j];
        out[(size_t)which * 64 * HDIM + (size_t)b * HDIM + j] = s + bias;
    }
}

// ---------------- launch ----------------
extern "C" void kernel_launch(void* const* d_in, const int* in_sizes, int n_in,
                              void* d_out, int out_size)
{
    (void)in_sizes; (void)n_in; (void)out_size;
    const int*   comments = (const int*)  d_in[0];
    const int*   cmids    = (const int*)  d_in[1];
    const int*   issue    = (const int*)  d_in[2];
    const float* emb_sc   = (const float*)d_in[3];
    const float* emb_cm   = (const float*)d_in[4];
    const float* emb_is   = (const float*)d_in[5];
    const float* Wih_sc   = (const float*)d_in[6];
    const float* Whh_sc   = (const float*)d_in[7];
    const float* b_sc     = (const float*)d_in[8];
    const float* Wih_cm   = (const float*)d_in[9];
    const float* Whh_cm   = (const float*)d_in[10];
    const float* b_cm     = (const float*)d_in[11];
    const float* Wih_is   = (const float*)d_in[12];
    const float* Whh_is   = (const float*)d_in[13];
    const float* b_is     = (const float*)d_in[14];
    const float* Wmh      = (const float*)d_in[15];
    const float* bmh      = (const float*)d_in[16];
    const float* Wmc      = (const float*)d_in[17];
    const float* bmc      = (const float*)d_in[18];
    const float* Wfh      = (const float*)d_in[19];
    const float* bfh      = (const float*)d_in[20];
    const float* Wfc      = (const float*)d_in[21];
    const float* bfc      = (const float*)d_in[22];

    zero_state<<<(N_SC * HDIM + 255) / 256, 256>>>();

    // input projections (parallel GEMMs, bias folded)
    xproj_kernel<<<dim3((N_SC * T_SC) / 64, 32), 256>>>(comments, emb_sc, Wih_sc, b_sc, N_SC, T_SC, 0);
    xproj_kernel<<<dim3((N_CM * T_CM) / 64, 32), 256>>>(cmids,    emb_cm, Wih_cm, b_cm, N_CM, T_CM, 1);
    xproj_kernel<<<dim3((N_IS * T_IS) / 64, 32), 256>>>(issue,    emb_is, Wih_is, b_is, N_IS, T_IS, 2);

    // recurrent steps: sc (128), cm (64) and is (32) ride in the same launches
    for (int t = 0; t < T_SC; t++) {
        int blocks = 160 + ((t < T_CM) ? 160 : 0) + ((t < T_IS) ? 16 : 0);
        lstm_step_all<<<blocks, 256>>>(t, Whh_sc, Whh_cm, Whh_is);
    }

    merge_kernel<<<(2 * N_SC * 32 + 255) / 256, 256>>>(Wmh, bmh, Wmc, bmc);
    final_kernel<<<(2 * 64 * HDIM * 32 + 255) / 256, 256>>>(Wfh, bfh, Wfc, bfc, (float*)d_out);
}